// round 1
// baseline (speedup 1.0000x reference)
#include <cuda_runtime.h>
#include <cstdint>

// e4m3 fake-quantize, calibrated scale:  out = Q(x/s) * s
//   Q(y): e = max(floor(log2|y|), -6); lsb = 2^(e-3);
//         q = min(rne(|y|/lsb)*lsb, 240); return sign(y)*q
// HBM-bound elementwise: float4 streaming.

__device__ __forceinline__ float fq_e4m3(float x, float s) {
    float y = x / s;
    float ay = fabsf(y);
    // floor(log2(ay)) via exponent bits (exact). ay==0 -> e=-127 -> clamped.
    int e = ((__float_as_int(ay) >> 23) & 0xFF) - 127;
    e = max(e, -6);
    // lsb = 2^(e-3); e-3 in [-9, ...], biased exponent positive -> exact construction
    float lsb = __int_as_float((e - 3 + 127) << 23);
    float q = rintf(ay / lsb) * lsb;     // RN mode => round-half-to-even (matches jnp.round)
    q = fminf(q, 240.0f);
    return copysignf(q, y) * s;
}

__global__ void __launch_bounds__(256) fq_kernel(const float4* __restrict__ x,
                                                 const float* __restrict__ scale,
                                                 float4* __restrict__ out,
                                                 long long n4) {
    long long i = (long long)blockIdx.x * blockDim.x + threadIdx.x;
    if (i >= n4) return;
    float s = __ldg(scale);
    float4 v = x[i];
    float4 r;
    r.x = fq_e4m3(v.x, s);
    r.y = fq_e4m3(v.y, s);
    r.z = fq_e4m3(v.z, s);
    r.w = fq_e4m3(v.w, s);
    out[i] = r;
}

// Tail kernel for non-multiple-of-4 sizes (not expected here, but safe).
__global__ void fq_tail(const float* __restrict__ x, const float* __restrict__ scale,
                        float* __restrict__ out, long long start, long long n) {
    long long i = start + blockIdx.x * blockDim.x + threadIdx.x;
    if (i >= n) return;
    out[i] = fq_e4m3(x[i], __ldg(scale));
}

extern "C" void kernel_launch(void* const* d_in, const int* in_sizes, int n_in,
                              void* d_out, int out_size) {
    const float* x = (const float*)d_in[0];
    const float* scale = (const float*)d_in[1];
    float* out = (float*)d_out;
    long long n = (long long)in_sizes[0];

    long long n4 = n >> 2;
    if (n4 > 0) {
        int threads = 256;
        long long blocks = (n4 + threads - 1) / threads;
        fq_kernel<<<(unsigned int)blocks, threads>>>(
            (const float4*)x, scale, (float4*)out, n4);
    }
    long long done = n4 << 2;
    if (done < n) {
        long long rem = n - done;
        fq_tail<<<(unsigned int)((rem + 255) / 256), 256>>>(x, scale, out, done, n);
    }
}

// round 2
// speedup vs baseline: 1.1480x; 1.1480x over previous
#include <cuda_runtime.h>
#include <cstdint>

// e4m3 fake-quantize: out = Q(x * (1/s)) * s
//   Q(y): e = max(floor(log2|y|), -6); lsb = 2^(e-3);
//         q = min(rne(|y| * 2^(3-e)) * lsb, 240); sign-restore.
// Division-free: lsb and inv_lsb are exact powers of two built from exponent bits.
// HBM-bound streaming: 4x float4 per thread, front-batched loads (MLP=4).

__device__ __forceinline__ float fq_e4m3(float x, float s_inv, float s) {
    float y = x * s_inv;
    float ay = fabsf(y);
    // floor(log2(ay)) via exponent field (exact; ay==0 -> -127 -> clamped to -6)
    int e = ((__float_as_int(ay) >> 23) & 0xFF) - 127;
    e = max(e, -6);
    float lsb     = __int_as_float((e - 3 + 127) << 23);  // 2^(e-3), exact
    float inv_lsb = __int_as_float((3 - e + 127) << 23);  // 2^(3-e), exact
    float q = rintf(ay * inv_lsb) * lsb;  // RN => round-half-even (matches jnp.round)
    q = fminf(q, 240.0f);
    return copysignf(q, y) * s;
}

__global__ void __launch_bounds__(256) fq_kernel4(const float4* __restrict__ x,
                                                  const float* __restrict__ scale,
                                                  float4* __restrict__ out,
                                                  long long n4) {
    // Each block owns a contiguous tile of 4*256 float4s; each thread does 4,
    // strided by blockDim for coalescing. Loads batched before any compute.
    long long base = (long long)blockIdx.x * (256 * 4) + threadIdx.x;

    float s = __ldg(scale);
    float s_inv = 1.0f / s;   // one true divide per thread, amortized over 16 elems

    float4 v0, v1, v2, v3;
    long long i0 = base;
    long long i1 = base + 256;
    long long i2 = base + 512;
    long long i3 = base + 768;
    bool p0 = i0 < n4, p1 = i1 < n4, p2 = i2 < n4, p3 = i3 < n4;
    if (p0) v0 = x[i0];
    if (p1) v1 = x[i1];
    if (p2) v2 = x[i2];
    if (p3) v3 = x[i3];

    float4 r;
    if (p0) {
        r.x = fq_e4m3(v0.x, s_inv, s); r.y = fq_e4m3(v0.y, s_inv, s);
        r.z = fq_e4m3(v0.z, s_inv, s); r.w = fq_e4m3(v0.w, s_inv, s);
        out[i0] = r;
    }
    if (p1) {
        r.x = fq_e4m3(v1.x, s_inv, s); r.y = fq_e4m3(v1.y, s_inv, s);
        r.z = fq_e4m3(v1.z, s_inv, s); r.w = fq_e4m3(v1.w, s_inv, s);
        out[i1] = r;
    }
    if (p2) {
        r.x = fq_e4m3(v2.x, s_inv, s); r.y = fq_e4m3(v2.y, s_inv, s);
        r.z = fq_e4m3(v2.z, s_inv, s); r.w = fq_e4m3(v2.w, s_inv, s);
        out[i2] = r;
    }
    if (p3) {
        r.x = fq_e4m3(v3.x, s_inv, s); r.y = fq_e4m3(v3.y, s_inv, s);
        r.z = fq_e4m3(v3.z, s_inv, s); r.w = fq_e4m3(v3.w, s_inv, s);
        out[i3] = r;
    }
}

// Scalar tail for non-multiple-of-4 element counts (not expected for 2^27).
__global__ void fq_tail(const float* __restrict__ x, const float* __restrict__ scale,
                        float* __restrict__ out, long long start, long long n) {
    long long i = start + blockIdx.x * blockDim.x + threadIdx.x;
    if (i >= n) return;
    float s = __ldg(scale);
    out[i] = fq_e4m3(x[i], 1.0f / s, s);
}

extern "C" void kernel_launch(void* const* d_in, const int* in_sizes, int n_in,
                              void* d_out, int out_size) {
    const float* x = (const float*)d_in[0];
    const float* scale = (const float*)d_in[1];
    float* out = (float*)d_out;
    long long n = (long long)in_sizes[0];

    long long n4 = n >> 2;
    if (n4 > 0) {
        const int threads = 256;
        const long long per_block = threads * 4;
        long long blocks = (n4 + per_block - 1) / per_block;
        fq_kernel4<<<(unsigned int)blocks, threads>>>(
            (const float4*)x, scale, (float4*)out, n4);
    }
    long long done = n4 << 2;
    if (done < n) {
        long long rem = n - done;
        fq_tail<<<(unsigned int)((rem + 255) / 256), 256>>>(x, scale, out, done, n);
    }
}

// round 3
// speedup vs baseline: 1.1482x; 1.0002x over previous
#include <cuda_runtime.h>
#include <cstdint>

// e4m3 fake-quantize: out = Q(x * (1/s)) * s
//   Q(y): e = max(floor(log2|y|), -6); lsb = 2^(e-3);
//         q = min(rne(|y| * 2^(3-e)) * lsb, 240); sign-restore.
// Division-free, exact (rel_err 0.0 vs reference).
// HBM streaming: 8x float4 per thread, front-batched loads (MLP=8),
// __ldcs/__stcs streaming cache hints to avoid L2 thrash.

__device__ __forceinline__ float fq_e4m3(float x, float s_inv, float s) {
    float y = x * s_inv;
    float ay = fabsf(y);
    int e = ((__float_as_int(ay) >> 23) & 0xFF) - 127;   // floor(log2|y|), exact
    e = max(e, -6);
    float lsb     = __int_as_float((e - 3 + 127) << 23); // 2^(e-3), exact
    float inv_lsb = __int_as_float((3 - e + 127) << 23); // 2^(3-e), exact
    float q = rintf(ay * inv_lsb) * lsb;  // RN => round-half-even (matches jnp.round)
    q = fminf(q, 240.0f);
    return copysignf(q, y) * s;
}

__device__ __forceinline__ float4 fq4(float4 v, float s_inv, float s) {
    float4 r;
    r.x = fq_e4m3(v.x, s_inv, s);
    r.y = fq_e4m3(v.y, s_inv, s);
    r.z = fq_e4m3(v.z, s_inv, s);
    r.w = fq_e4m3(v.w, s_inv, s);
    return r;
}

#define VPT 8   // float4s per thread

__global__ void __launch_bounds__(256) fq_kernel8(const float4* __restrict__ x,
                                                  const float* __restrict__ scale,
                                                  float4* __restrict__ out,
                                                  long long n4) {
    long long base = (long long)blockIdx.x * (256 * VPT) + threadIdx.x;

    float s = __ldg(scale);
    float s_inv = 1.0f / s;

    float4 v[VPT];
    bool p[VPT];
    // Front-batched streaming loads: MLP_p1 = 8
#pragma unroll
    for (int j = 0; j < VPT; j++) {
        long long i = base + (long long)j * 256;
        p[j] = i < n4;
        if (p[j]) v[j] = __ldcs(&x[i]);
    }
#pragma unroll
    for (int j = 0; j < VPT; j++) {
        if (p[j]) {
            long long i = base + (long long)j * 256;
            __stcs(&out[i], fq4(v[j], s_inv, s));
        }
    }
}

// Scalar tail for non-multiple-of-4 element counts (not expected for 2^27).
__global__ void fq_tail(const float* __restrict__ x, const float* __restrict__ scale,
                        float* __restrict__ out, long long start, long long n) {
    long long i = start + blockIdx.x * blockDim.x + threadIdx.x;
    if (i >= n) return;
    float s = __ldg(scale);
    out[i] = fq_e4m3(x[i], 1.0f / s, s);
}

extern "C" void kernel_launch(void* const* d_in, const int* in_sizes, int n_in,
                              void* d_out, int out_size) {
    const float* x = (const float*)d_in[0];
    const float* scale = (const float*)d_in[1];
    float* out = (float*)d_out;
    long long n = (long long)in_sizes[0];

    long long n4 = n >> 2;
    if (n4 > 0) {
        const int threads = 256;
        const long long per_block = threads * VPT;
        long long blocks = (n4 + per_block - 1) / per_block;
        fq_kernel8<<<(unsigned int)blocks, threads>>>(
            (const float4*)x, scale, (float4*)out, n4);
    }
    long long done = n4 << 2;
    if (done < n) {
        long long rem = n - done;
        fq_tail<<<(unsigned int)((rem + 255) / 256), 256>>>(x, scale, out, done, n);
    }
}

// round 4
// speedup vs baseline: 1.1527x; 1.0039x over previous
#include <cuda_runtime.h>
#include <cstdint>

// e4m3 fake-quantize: out = Q(x * (1/s)) * s
//   Q(y): e = max(floor(log2|y|), -6); lsb = 2^(e-3);
//         q = min(rne(|y| * 2^(3-e)) * lsb, 240); sign-restore.
// Division-free, exact (rel_err 0.0 vs reference).
// HBM-ceiling streaming kernel: 8x float4/thread front-batched (MLP=8),
// __ldcs/__stcs, exact-path variant with zero predicates and 32-bit
// byte-offset indexing for the (common) exactly-divisible shape.

__device__ __forceinline__ float fq_e4m3(float x, float s_inv, float s) {
    float y = x * s_inv;
    float ay = fabsf(y);
    int e = ((__float_as_int(ay) >> 23) & 0xFF) - 127;   // floor(log2|y|), exact
    e = max(e, -6);
    float lsb     = __int_as_float((e - 3 + 127) << 23); // 2^(e-3), exact
    float inv_lsb = __int_as_float((3 - e + 127) << 23); // 2^(3-e), exact
    float q = rintf(ay * inv_lsb) * lsb;  // RN => round-half-even (matches jnp.round)
    q = fminf(q, 240.0f);
    return copysignf(q, y) * s;
}

__device__ __forceinline__ float4 fq4(float4 v, float s_inv, float s) {
    float4 r;
    r.x = fq_e4m3(v.x, s_inv, s);
    r.y = fq_e4m3(v.y, s_inv, s);
    r.z = fq_e4m3(v.z, s_inv, s);
    r.w = fq_e4m3(v.w, s_inv, s);
    return r;
}

#define VPT 8   // float4s per thread
#define TPB 256

// Exact path: n4 % (TPB*VPT) == 0 and total bytes < 2^31. No predicates,
// u32 byte-offset addressing (single IMAD per access).
__global__ void __launch_bounds__(TPB) fq_exact(const char* __restrict__ xb,
                                                const float* __restrict__ scale,
                                                char* __restrict__ ob) {
    unsigned base = (blockIdx.x * (TPB * VPT) + threadIdx.x) * 16u;

    float s = __ldg(scale);
    float s_inv = 1.0f / s;

    float4 v[VPT];
#pragma unroll
    for (int j = 0; j < VPT; j++)
        v[j] = __ldcs((const float4*)(xb + base + j * (TPB * 16u)));
#pragma unroll
    for (int j = 0; j < VPT; j++)
        __stcs((float4*)(ob + base + j * (TPB * 16u)), fq4(v[j], s_inv, s));
}

// Generic fallback (any n multiple of 4).
__global__ void __launch_bounds__(TPB) fq_generic(const float4* __restrict__ x,
                                                  const float* __restrict__ scale,
                                                  float4* __restrict__ out,
                                                  long long n4) {
    long long base = (long long)blockIdx.x * (TPB * VPT) + threadIdx.x;
    float s = __ldg(scale);
    float s_inv = 1.0f / s;
#pragma unroll
    for (int j = 0; j < VPT; j++) {
        long long i = base + (long long)j * TPB;
        if (i < n4) __stcs(&out[i], fq4(__ldcs(&x[i]), s_inv, s));
    }
}

// Scalar tail for non-multiple-of-4 element counts.
__global__ void fq_tail(const float* __restrict__ x, const float* __restrict__ scale,
                        float* __restrict__ out, long long start, long long n) {
    long long i = start + blockIdx.x * blockDim.x + threadIdx.x;
    if (i >= n) return;
    float s = __ldg(scale);
    out[i] = fq_e4m3(x[i], 1.0f / s, s);
}

extern "C" void kernel_launch(void* const* d_in, const int* in_sizes, int n_in,
                              void* d_out, int out_size) {
    const float* x = (const float*)d_in[0];
    const float* scale = (const float*)d_in[1];
    float* out = (float*)d_out;
    long long n = (long long)in_sizes[0];

    long long n4 = n >> 2;
    const long long per_block = (long long)TPB * VPT;

    if (n4 > 0 && (n4 % per_block) == 0 && n * 4ll < (1ll << 31)) {
        unsigned blocks = (unsigned)(n4 / per_block);
        fq_exact<<<blocks, TPB>>>((const char*)x, scale, (char*)out);
    } else if (n4 > 0) {
        long long blocks = (n4 + per_block - 1) / per_block;
        fq_generic<<<(unsigned)blocks, TPB>>>((const float4*)x, scale, (float4*)out, n4);
    }
    long long done = n4 << 2;
    if (done < n) {
        long long rem = n - done;
        fq_tail<<<(unsigned)((rem + 255) / 256), 256>>>(x, scale, out, done, n);
    }
}